// round 6
// baseline (speedup 1.0000x reference)
#include <cuda_runtime.h>
#include <math.h>

#define Bv 4
#define Hv 16
#define Nv 8192
#define Dv 64
#define BH (Bv*Hv)
#define SPLIT1 16
#define SPLIT2 16

typedef unsigned long long u64;

// scratch (device globals: no allocation allowed)
__device__ float g_ctx[BH*Dv*Dv];    // [bh][d][e]
__device__ float g_v2sum[BH*Dv];     // [bh][d]
__device__ float g_f[BH*Nv];         // per-token denominator f

__device__ __forceinline__ float elu1(float x) {
    return x > 0.f ? x + 1.f : __expf(x);
}

// pack scalar into both lanes of f32x2
__device__ __forceinline__ u64 pk2(float v) {
    u64 r; asm("mov.b64 %0, {%1,%1};" : "=l"(r) : "f"(v)); return r;
}
// packed fma: d = a*b + c lanewise
__device__ __forceinline__ u64 f2(u64 a, u64 b, u64 c) {
    u64 d; asm("fma.rn.f32x2 %0, %1, %2, %3;" : "=l"(d) : "l"(a), "l"(b), "l"(c));
    return d;
}
__device__ __forceinline__ void upk(u64 v, float& lo, float& hi) {
    asm("mov.b64 {%0,%1}, %2;" : "=f"(lo), "=f"(hi) : "l"(v));
}
// 16B shared load directly into two packed f32x2 regs (no pack movs)
__device__ __forceinline__ void lds2(u64& a, u64& b, const float* p) {
    unsigned r = (unsigned)__cvta_generic_to_shared(p);
    asm volatile("ld.shared.v2.u64 {%0,%1}, [%2];" : "=l"(a), "=l"(b) : "r"(r));
}

__global__ void k0_zero() {
    int i = blockIdx.x*blockDim.x + threadIdx.x;
    if (i < BH*Dv*Dv) g_ctx[i] = 0.f;
    if (i < BH*Dv)    g_v2sum[i] = 0.f;
}

// Pass 1: from K,V compute v2, x, f; accumulate context = v2^T x and sum(v2).
__global__ __launch_bounds__(256) void k1_pass1(
        const float* __restrict__ Kin, const float* __restrict__ Vin,
        const float* __restrict__ mask, const float* __restrict__ curv) {
    const int bh = blockIdx.x;
    const int split = blockIdx.y;
    const float kc = curv[bh & (Hv-1)];
    const int tokens = Nv / SPLIT1;          // 512
    const int n0 = split * tokens;
    __shared__ __align__(16) float ks[32*68];   // K tile -> v2 tile
    __shared__ __align__(16) float vs[32*68];   // V tile -> x tile
    __shared__ float smv[Dv];
    const int tid = threadIdx.x;
    if (tid < Dv) smv[tid] = 0.f;
    const float* Kb = Kin + (size_t)bh*Nv*Dv;
    const float* Vb = Vin + (size_t)bh*Nv*Dv;

    // GEMM layout: two token-halves (tid>>7), within half 16 row-groups x 8 col-groups,
    // each thread owns rows gy*4..+3 (d) and cols gx*8..+7 (e), packed as 4 f32x2 pairs.
    const int gy = (tid & 127) >> 3;
    const int gx = tid & 7;
    const float* ksB = ks + (tid >> 7)*16*68;
    const float* vsB = vs + (tid >> 7)*16*68;

    u64 acc2[4][4];
    #pragma unroll
    for (int i=0;i<4;i++)
        #pragma unroll
        for (int j=0;j<4;j++) acc2[i][j]=0ull;
    float v2loc[8];
    #pragma unroll
    for (int j=0;j<8;j++) v2loc[j]=0.f;

    const int tB = tid >> 3, sub = tid & 7;   // phase-B: 32 tokens x 8 threads

    for (int c0 = 0; c0 < tokens; c0 += 32) {
        const int nb = n0 + c0;
        __syncthreads();
        // Phase A: coalesced load of 32x64 K and V tiles
        #pragma unroll
        for (int r = 0; r < 2; r++) {
            int j = tid + r*256;
            int t = j >> 4, d4 = (j & 15)*4;
            *(float4*)(ks + t*68 + d4) = *(const float4*)(Kb + (size_t)(nb+t)*Dv + d4);
            *(float4*)(vs + t*68 + d4) = *(const float4*)(Vb + (size_t)(nb+t)*Dv + d4);
        }
        __syncthreads();
        // Phase B: per-token scalars, overwrite tiles with v2 / x
        {
            const int n = nb + tB;
            float* vp = vs + tB*68 + sub*8;
            float* kp = ks + tB*68 + sub*8;
            float4 va  = *(float4*)vp;
            float4 vb4 = *(float4*)(vp+4);
            float ss = va.x*va.x + va.y*va.y + va.z*va.z + va.w*va.w
                     + vb4.x*vb4.x + vb4.y*vb4.y + vb4.z*vb4.z + vb4.w*vb4.w;
            ss += __shfl_xor_sync(0xffffffffu, ss, 1);
            ss += __shfl_xor_sync(0xffffffffu, ss, 2);
            ss += __shfl_xor_sync(0xffffffffu, ss, 4);
            float f = fmaxf(1.f + kc*ss, 1e-15f);
            float invf = 1.f / f;
            float gamma = 2.f * invf;
            float gm1 = gamma - 1.f;
            float dn = copysignf(fmaxf(fabsf(gm1), 1e-10f), gm1);  // clamp_abs
            float m = mask[n];
            float dm = dn * m;
            float gd = (gamma / dn) * m;
            float4 ka  = *(float4*)kp;
            float4 kb4 = *(float4*)(kp+4);
            float w0 = dm*elu1(ka.x*invf),  w1 = dm*elu1(ka.y*invf);
            float w2 = dm*elu1(ka.z*invf),  w3 = dm*elu1(ka.w*invf);
            float w4 = dm*elu1(kb4.x*invf), w5 = dm*elu1(kb4.y*invf);
            float w6 = dm*elu1(kb4.z*invf), w7 = dm*elu1(kb4.w*invf);
            *(float4*)kp     = make_float4(w0,w1,w2,w3);
            *(float4*)(kp+4) = make_float4(w4,w5,w6,w7);
            *(float4*)vp     = make_float4(gd*va.x,  gd*va.y,  gd*va.z,  gd*va.w);
            *(float4*)(vp+4) = make_float4(gd*vb4.x, gd*vb4.y, gd*vb4.z, gd*vb4.w);
            v2loc[0]+=w0; v2loc[1]+=w1; v2loc[2]+=w2; v2loc[3]+=w3;
            v2loc[4]+=w4; v2loc[5]+=w5; v2loc[6]+=w6; v2loc[7]+=w7;
            if (sub == 0) g_f[(size_t)bh*Nv + n] = f;
        }
        __syncthreads();
        // GEMM phase: context[d][e] += v2[t][d]*x[t][e], 4x8 per thread, f32x2 packed
        #pragma unroll
        for (int tt = 0; tt < 16; tt++) {
            float4 a = *(const float4*)(ksB + tt*68 + gy*4);
            u64 b0,b1,b2,b3;
            lds2(b0, b1, vsB + tt*68 + gx*8);
            lds2(b2, b3, vsB + tt*68 + gx*8 + 4);
            u64 a0 = pk2(a.x), a1 = pk2(a.y), a2 = pk2(a.z), a3 = pk2(a.w);
            acc2[0][0]=f2(a0,b0,acc2[0][0]); acc2[0][1]=f2(a0,b1,acc2[0][1]);
            acc2[0][2]=f2(a0,b2,acc2[0][2]); acc2[0][3]=f2(a0,b3,acc2[0][3]);
            acc2[1][0]=f2(a1,b0,acc2[1][0]); acc2[1][1]=f2(a1,b1,acc2[1][1]);
            acc2[1][2]=f2(a1,b2,acc2[1][2]); acc2[1][3]=f2(a1,b3,acc2[1][3]);
            acc2[2][0]=f2(a2,b0,acc2[2][0]); acc2[2][1]=f2(a2,b1,acc2[2][1]);
            acc2[2][2]=f2(a2,b2,acc2[2][2]); acc2[2][3]=f2(a2,b3,acc2[2][3]);
            acc2[3][0]=f2(a3,b0,acc2[3][0]); acc2[3][1]=f2(a3,b1,acc2[3][1]);
            acc2[3][2]=f2(a3,b2,acc2[3][2]); acc2[3][3]=f2(a3,b3,acc2[3][3]);
        }
    }
    // epilogue: merge partials (both halves merge via atomics)
    float* ctx = g_ctx + bh*Dv*Dv;
    #pragma unroll
    for (int i=0;i<4;i++) {
        #pragma unroll
        for (int j=0;j<4;j++) {
            float lo, hi; upk(acc2[i][j], lo, hi);
            atomicAdd(&ctx[(gy*4+i)*Dv + gx*8 + 2*j],     lo);
            atomicAdd(&ctx[(gy*4+i)*Dv + gx*8 + 2*j + 1], hi);
        }
    }
    __syncthreads();
    #pragma unroll
    for (int j=0;j<8;j++) atomicAdd(&smv[sub*8+j], v2loc[j]);
    __syncthreads();
    if (tid < Dv) atomicAdd(&g_v2sum[bh*Dv + tid], smv[tid]);
}

// Pass 2: v1, Dn, X = (v1@context)*Dinv, fused radial geometry, write out.
__global__ __launch_bounds__(256) void k2_pass2(
        const float* __restrict__ Qin, const float* __restrict__ curv,
        float* __restrict__ Out) {
    const int bh = blockIdx.x, split = blockIdx.y;
    const float kc = curv[bh & (Hv-1)];
    const float absk = fabsf(kc);
    const float sk = sqrtf(absk + 1e-15f);
    const float maxnorm = (kc < 0.f) ? (1.f - 0.004f)/sqrtf(absk + 1e-15f) : 1e15f;
    __shared__ __align__(16) float ctx_s[Dv*68];
    __shared__ __align__(16) float qv[Dv*68];     // Q tile, then reused as v1^T tile
    __shared__ float v2s[Dv];
    __shared__ float ffs[Dv];
    __shared__ float dinv[Dv];
    const int tid = threadIdx.x;
    for (int i = tid; i < Dv*Dv; i += 256)
        ctx_s[(i>>6)*68 + (i&63)] = g_ctx[bh*Dv*Dv + i];
    if (tid < Dv) v2s[tid] = g_v2sum[bh*Dv + tid];
    const float* Qb = Qin + (size_t)bh*Nv*Dv;
    float* Ob = Out + (size_t)bh*Nv*Dv;
    const int tokens = Nv / SPLIT2;   // 512
    const int n0 = split*tokens;
    const int tB = tid >> 2, sub = tid & 3;   // phase-B: 64 tokens x 4 threads
    const int gy = tid >> 3, gx = tid & 7;    // GEMM: 32 token-groups x 8 col-groups

    for (int c0 = 0; c0 < tokens; c0 += 64) {
        const int nb = n0 + c0;
        __syncthreads();
        // Phase A: coalesced 64x64 Q tile + f scalars
        #pragma unroll
        for (int r = 0; r < 4; r++) {
            int j = tid + r*256;
            int t = j >> 4, d4 = (j & 15)*4;
            *(float4*)(qv + t*68 + d4) = *(const float4*)(Qb + (size_t)(nb+t)*Dv + d4);
        }
        if (tid < Dv) ffs[tid] = g_f[(size_t)bh*Nv + nb + tid];
        __syncthreads();
        // Phase B: v1 into registers + Dn
        float invf = 1.f / ffs[tB];
        float v1r[16];
        float dnp = 0.f;
        #pragma unroll
        for (int r = 0; r < 4; r++) {
            int d0 = sub*16 + r*4;
            float4 q4 = *(float4*)(qv + tB*68 + d0);
            float e0 = elu1(q4.x*invf), e1 = elu1(q4.y*invf);
            float e2 = elu1(q4.z*invf), e3 = elu1(q4.w*invf);
            v1r[r*4+0]=e0; v1r[r*4+1]=e1; v1r[r*4+2]=e2; v1r[r*4+3]=e3;
            dnp += e0*v2s[d0] + e1*v2s[d0+1] + e2*v2s[d0+2] + e3*v2s[d0+3];
        }
        dnp += __shfl_xor_sync(0xffffffffu, dnp, 1);
        dnp += __shfl_xor_sync(0xffffffffu, dnp, 2);
        if (sub == 0) dinv[tB] = 1.f / ((dnp == 0.f) ? 1e-5f : dnp);
        __syncthreads();   // all reads of qv done; now overwrite with v1^T
        #pragma unroll
        for (int r = 0; r < 16; r++) {
            int d = sub*16 + r;
            qv[d*68 + tB] = v1r[r];
        }
        __syncthreads();
        // GEMM: X[t][e] = sum_d v1[t][d]*ctx[d][e], 2 tokens x 8 cols per thread, f32x2
        u64 acc2[2][4];
        #pragma unroll
        for (int i=0;i<2;i++)
            #pragma unroll
            for (int j=0;j<4;j++) acc2[i][j]=0ull;
        #pragma unroll 16
        for (int d = 0; d < Dv; d++) {
            float2 a = *(const float2*)(qv + d*68 + gy*2);
            u64 b0,b1,b2,b3;
            lds2(b0, b1, ctx_s + d*68 + gx*8);
            lds2(b2, b3, ctx_s + d*68 + gx*8 + 4);
            u64 a0 = pk2(a.x), a1 = pk2(a.y);
            acc2[0][0]=f2(a0,b0,acc2[0][0]); acc2[0][1]=f2(a0,b1,acc2[0][1]);
            acc2[0][2]=f2(a0,b2,acc2[0][2]); acc2[0][3]=f2(a0,b3,acc2[0][3]);
            acc2[1][0]=f2(a1,b0,acc2[1][0]); acc2[1][1]=f2(a1,b1,acc2[1][1]);
            acc2[1][2]=f2(a1,b2,acc2[1][2]); acc2[1][3]=f2(a1,b3,acc2[1][3]);
        }
        // epilogue: D_inv scale + radial geometry (project, mobius 0.5, project)
        #pragma unroll
        for (int i = 0; i < 2; i++) {
            int t = gy*2 + i;
            float di = dinv[t];
            float x[8];
            #pragma unroll
            for (int j = 0; j < 4; j++) {
                float lo, hi; upk(acc2[i][j], lo, hi);
                x[2*j] = lo*di; x[2*j+1] = hi*di;
            }
            float ss = 0.f;
            #pragma unroll
            for (int j = 0; j < 8; j++) ss += x[j]*x[j];
            ss += __shfl_xor_sync(0xffffffffu, ss, 1);
            ss += __shfl_xor_sync(0xffffffffu, ss, 2);
            ss += __shfl_xor_sync(0xffffffffu, ss, 4);
            float norm = fmaxf(sqrtf(ss), 1e-15f);
            float s = 1.f, n1 = norm;
            if (norm > maxnorm) { s = maxnorm/norm; n1 = maxnorm; }
            float xn = fmaxf(n1, 1e-15f);
            float tv;
            if (kc < 0.f) {
                // tanh(0.5*artanh(z))/sk == z/((1+sqrt(1-z^2))*sk)
                float z = fminf(sk*xn, 1.f - 1e-7f);
                tv = z / ((1.f + sqrtf(fmaxf(1.f - z*z, 0.f))) * sk);
            } else {
                tv = tanf(0.5f * atanf(sk*xn)) / sk;
            }
            s *= tv / xn;
            float n2 = fabsf(tv);
            if (n2 > maxnorm) s *= maxnorm/n2;
            float* op = Ob + (size_t)(nb+t)*Dv + gx*8;
            *(float4*)op     = make_float4(x[0]*s, x[1]*s, x[2]*s, x[3]*s);
            *(float4*)(op+4) = make_float4(x[4]*s, x[5]*s, x[6]*s, x[7]*s);
        }
    }
}

extern "C" void kernel_launch(void* const* d_in, const int* in_sizes, int n_in,
                              void* d_out, int out_size) {
    const float* Q    = (const float*)d_in[0];
    const float* K    = (const float*)d_in[1];
    const float* V    = (const float*)d_in[2];
    const float* mask = (const float*)d_in[3];
    const float* curv = (const float*)d_in[4];
    float* out = (float*)d_out;
    (void)in_sizes; (void)n_in; (void)out_size;

    k0_zero<<<(BH*Dv*Dv + 255)/256, 256>>>();
    k1_pass1<<<dim3(BH, SPLIT1), 256>>>(K, V, mask, curv);
    k2_pass2<<<dim3(BH, SPLIT2), 256>>>(Q, curv, out);
}

// round 13
// speedup vs baseline: 1.5269x; 1.5269x over previous
#include <cuda_runtime.h>
#include <math.h>

#define Bv 4
#define Hv 16
#define Nv 8192
#define Dv 64
#define BH (Bv*Hv)
#define SPLIT1 8
#define SPLIT2 8

// scratch (device globals: no allocation allowed)
__device__ float g_ctx[BH*Dv*Dv];    // [bh][d][e]
__device__ float g_v2sum[BH*Dv];     // [bh][d]
__device__ float g_f[BH*Nv];         // per-token denominator f

// elu(x)+1 without MUFU: x>0 -> x+1, else exp(x) via deg-5 exp2 poly.
// Magic-number rounding + exponent bit-trick keeps everything on fma/alu pipes.
__device__ __forceinline__ float elu1(float x) {
    float y = fmaxf(x, -80.f) * 1.442695041f;     // log2(e)
    float r = y + 12582912.f;                     // round-to-nearest-int (RN magic)
    int   i = __float_as_int(r);
    float f = y - (r - 12582912.f);               // f in [-0.5, 0.5]
    float p = 0.00133335581f;                     // ln2^5/120
    p = fmaf(p, f, 0.00961812911f);               // ln2^4/24
    p = fmaf(p, f, 0.0555041087f);                // ln2^3/6
    p = fmaf(p, f, 0.240226507f);                 // ln2^2/2
    p = fmaf(p, f, 0.693147181f);                 // ln2
    p = fmaf(p, f, 1.0f);
    float sc = __int_as_float((i << 23) + 0x3f800000);  // 2^n
    float e = p * sc;
    return x > 0.f ? x + 1.f : e;
}

__global__ void k0_zero() {
    int i = blockIdx.x*blockDim.x + threadIdx.x;
    if (i < BH*Dv*Dv) g_ctx[i] = 0.f;
    if (i < BH*Dv)    g_v2sum[i] = 0.f;
}

// Pass 1: from K,V compute v2, x, f; accumulate context = v2^T x and sum(v2).
__global__ __launch_bounds__(256) void k1_pass1(
        const float* __restrict__ Kin, const float* __restrict__ Vin,
        const float* __restrict__ mask, const float* __restrict__ curv) {
    const int bh = blockIdx.x;
    const int split = blockIdx.y;
    const float kc = curv[bh & (Hv-1)];
    const int tokens = Nv / SPLIT1;          // 1024
    const int n0 = split * tokens;
    __shared__ __align__(16) float ks[32*68];   // K tile -> v2 tile
    __shared__ __align__(16) float vs[32*68];   // V tile -> x tile
    __shared__ float smv[Dv];
    const int tid = threadIdx.x;
    if (tid < Dv) smv[tid] = 0.f;
    const float* Kb = Kin + (size_t)bh*Nv*Dv;
    const float* Vb = Vin + (size_t)bh*Nv*Dv;

    float acc[4][4];
    #pragma unroll
    for (int i=0;i<4;i++)
        #pragma unroll
        for (int j=0;j<4;j++) acc[i][j]=0.f;
    float v2loc[8];
    #pragma unroll
    for (int j=0;j<8;j++) v2loc[j]=0.f;

    const int tB = tid >> 3, sub = tid & 7;   // 32 tokens x 8 threads
    const int ty = tid >> 4, tx = tid & 15;   // 16x16 GEMM grid

    for (int c0 = 0; c0 < tokens; c0 += 32) {
        const int nb = n0 + c0;
        __syncthreads();
        // Phase A: coalesced load of 32x64 K and V tiles
        #pragma unroll
        for (int r = 0; r < 2; r++) {
            int j = tid + r*256;
            int t = j >> 4, d4 = (j & 15)*4;
            *(float4*)(ks + t*68 + d4) = *(const float4*)(Kb + (size_t)(nb+t)*Dv + d4);
            *(float4*)(vs + t*68 + d4) = *(const float4*)(Vb + (size_t)(nb+t)*Dv + d4);
        }
        __syncthreads();
        // Phase B: per-token scalars, overwrite tiles with v2 / x
        {
            const int n = nb + tB;
            float* vp = vs + tB*68 + sub*8;
            float* kp = ks + tB*68 + sub*8;
            float4 va  = *(float4*)vp;
            float4 vb4 = *(float4*)(vp+4);
            float ss = va.x*va.x + va.y*va.y + va.z*va.z + va.w*va.w
                     + vb4.x*vb4.x + vb4.y*vb4.y + vb4.z*vb4.z + vb4.w*vb4.w;
            ss += __shfl_xor_sync(0xffffffffu, ss, 1);
            ss += __shfl_xor_sync(0xffffffffu, ss, 2);
            ss += __shfl_xor_sync(0xffffffffu, ss, 4);
            float f = fmaxf(1.f + kc*ss, 1e-15f);
            float invf = 1.f / f;
            float gamma = 2.f * invf;
            float gm1 = gamma - 1.f;
            float dn = copysignf(fmaxf(fabsf(gm1), 1e-10f), gm1);  // clamp_abs
            float m = mask[n];
            float dm = dn * m;
            float gd = (gamma / dn) * m;
            float4 ka  = *(float4*)kp;
            float4 kb4 = *(float4*)(kp+4);
            float w0 = dm*elu1(ka.x*invf),  w1 = dm*elu1(ka.y*invf);
            float w2 = dm*elu1(ka.z*invf),  w3 = dm*elu1(ka.w*invf);
            float w4 = dm*elu1(kb4.x*invf), w5 = dm*elu1(kb4.y*invf);
            float w6 = dm*elu1(kb4.z*invf), w7 = dm*elu1(kb4.w*invf);
            *(float4*)kp     = make_float4(w0,w1,w2,w3);
            *(float4*)(kp+4) = make_float4(w4,w5,w6,w7);
            *(float4*)vp     = make_float4(gd*va.x,  gd*va.y,  gd*va.z,  gd*va.w);
            *(float4*)(vp+4) = make_float4(gd*vb4.x, gd*vb4.y, gd*vb4.z, gd*vb4.w);
            v2loc[0]+=w0; v2loc[1]+=w1; v2loc[2]+=w2; v2loc[3]+=w3;
            v2loc[4]+=w4; v2loc[5]+=w5; v2loc[6]+=w6; v2loc[7]+=w7;
            if (sub == 0) g_f[(size_t)bh*Nv + n] = f;
        }
        __syncthreads();
        // GEMM phase: context[d][e] += v2[t][d]*x[t][e], 4x4 per thread
        #pragma unroll 8
        for (int t = 0; t < 32; t++) {
            float4 a = *(float4*)(ks + t*68 + ty*4);
            float4 b = *(float4*)(vs + t*68 + tx*4);
            float av[4] = {a.x,a.y,a.z,a.w};
            float bw[4] = {b.x,b.y,b.z,b.w};
            #pragma unroll
            for (int i=0;i<4;i++)
                #pragma unroll
                for (int j=0;j<4;j++) acc[i][j] += av[i]*bw[j];
        }
    }
    // epilogue: merge partials
    float* ctx = g_ctx + bh*Dv*Dv;
    #pragma unroll
    for (int i=0;i<4;i++)
        #pragma unroll
        for (int j=0;j<4;j++)
            atomicAdd(&ctx[(ty*4+i)*Dv + tx*4+j], acc[i][j]);
    __syncthreads();
    #pragma unroll
    for (int j=0;j<8;j++) atomicAdd(&smv[sub*8+j], v2loc[j]);
    __syncthreads();
    if (tid < Dv) atomicAdd(&g_v2sum[bh*Dv + tid], smv[tid]);
}

// Pass 2: v1, Dn, X = (v1@context)*Dinv, fused radial geometry, write out.
__global__ __launch_bounds__(256) void k2_pass2(
        const float* __restrict__ Qin, const float* __restrict__ curv,
        float* __restrict__ Out) {
    const int bh = blockIdx.x, split = blockIdx.y;
    const float kc = curv[bh & (Hv-1)];
    const float absk = fabsf(kc);
    const float sk = sqrtf(absk + 1e-15f);
    const float maxnorm = (kc < 0.f) ? (1.f - 0.004f)/sqrtf(absk + 1e-15f) : 1e15f;
    __shared__ __align__(16) float ctx_s[Dv*68];
    __shared__ __align__(16) float qv[Dv*68];     // Q tile, then reused as v1^T tile
    __shared__ float v2s[Dv];
    __shared__ float ffs[Dv];
    __shared__ float dinv[Dv];
    const int tid = threadIdx.x;
    for (int i = tid; i < Dv*Dv; i += 256)
        ctx_s[(i>>6)*68 + (i&63)] = g_ctx[bh*Dv*Dv + i];
    if (tid < Dv) v2s[tid] = g_v2sum[bh*Dv + tid];
    const float* Qb = Qin + (size_t)bh*Nv*Dv;
    float* Ob = Out + (size_t)bh*Nv*Dv;
    const int tokens = Nv / SPLIT2;
    const int n0 = split*tokens;
    const int tB = tid >> 2, sub = tid & 3;   // 64 tokens x 4 threads
    const int ty = tid >> 4, tx = tid & 15;

    for (int c0 = 0; c0 < tokens; c0 += 64) {
        const int nb = n0 + c0;
        __syncthreads();
        // Phase A: coalesced 64x64 Q tile + f scalars
        #pragma unroll
        for (int r = 0; r < 4; r++) {
            int j = tid + r*256;
            int t = j >> 4, d4 = (j & 15)*4;
            *(float4*)(qv + t*68 + d4) = *(const float4*)(Qb + (size_t)(nb+t)*Dv + d4);
        }
        if (tid < Dv) ffs[tid] = g_f[(size_t)bh*Nv + nb + tid];
        __syncthreads();
        // Phase B: v1 into registers + Dn
        float invf = 1.f / ffs[tB];
        float v1r[16];
        float dnp = 0.f;
        #pragma unroll
        for (int r = 0; r < 4; r++) {
            int d0 = sub*16 + r*4;
            float4 q4 = *(float4*)(qv + tB*68 + d0);
            float e0 = elu1(q4.x*invf), e1 = elu1(q4.y*invf);
            float e2 = elu1(q4.z*invf), e3 = elu1(q4.w*invf);
            v1r[r*4+0]=e0; v1r[r*4+1]=e1; v1r[r*4+2]=e2; v1r[r*4+3]=e3;
            dnp += e0*v2s[d0] + e1*v2s[d0+1] + e2*v2s[d0+2] + e3*v2s[d0+3];
        }
        dnp += __shfl_xor_sync(0xffffffffu, dnp, 1);
        dnp += __shfl_xor_sync(0xffffffffu, dnp, 2);
        if (sub == 0) dinv[tB] = 1.f / ((dnp == 0.f) ? 1e-5f : dnp);
        __syncthreads();   // all reads of qv done; now overwrite with v1^T
        #pragma unroll
        for (int r = 0; r < 16; r++) {
            int d = sub*16 + r;
            qv[d*68 + tB] = v1r[r];
        }
        __syncthreads();
        // GEMM: X[t][e] = sum_d v1[t][d]*ctx[d][e], 4 tokens x 4 dims per thread
        float acc[4][4];
        #pragma unroll
        for (int i=0;i<4;i++)
            #pragma unroll
            for (int j=0;j<4;j++) acc[i][j]=0.f;
        #pragma unroll 16
        for (int d = 0; d < Dv; d++) {
            float4 a = *(float4*)(qv + d*68 + ty*4);
            float4 b = *(float4*)(ctx_s + d*68 + tx*4);
            float av[4] = {a.x,a.y,a.z,a.w};
            float bw[4] = {b.x,b.y,b.z,b.w};
            #pragma unroll
            for (int i=0;i<4;i++)
                #pragma unroll
                for (int j=0;j<4;j++) acc[i][j] += av[i]*bw[j];
        }
        // epilogue: D_inv scale + radial geometry (project, mobius 0.5, project)
        #pragma unroll
        for (int i = 0; i < 4; i++) {
            int t = ty*4 + i;
            float di = dinv[t];
            float x0 = acc[i][0]*di, x1 = acc[i][1]*di;
            float x2 = acc[i][2]*di, x3 = acc[i][3]*di;
            float ss = x0*x0 + x1*x1 + x2*x2 + x3*x3;
            ss += __shfl_xor_sync(0xffffffffu, ss, 1);
            ss += __shfl_xor_sync(0xffffffffu, ss, 2);
            ss += __shfl_xor_sync(0xffffffffu, ss, 4);
            ss += __shfl_xor_sync(0xffffffffu, ss, 8);
            float norm = fmaxf(sqrtf(ss), 1e-15f);
            float s = 1.f, n1 = norm;
            if (norm > maxnorm) { s = maxnorm/norm; n1 = maxnorm; }
            float xn = fmaxf(n1, 1e-15f);
            float tv;
            if (kc < 0.f) {
                // tanh(0.5*artanh(z))/sk == z/((1+sqrt(1-z^2))*sk)
                float z = fminf(sk*xn, 1.f - 1e-7f);
                tv = z / ((1.f + sqrtf(fmaxf(1.f - z*z, 0.f))) * sk);
            } else {
                tv = tanf(0.5f * atanf(sk*xn)) / sk;
            }
            s *= tv / xn;
            float n2 = fabsf(tv);
            if (n2 > maxnorm) s *= maxnorm/n2;
            *(float4*)(Ob + (size_t)(nb+t)*Dv + tx*4) =
                make_float4(x0*s, x1*s, x2*s, x3*s);
        }
    }
}

extern "C" void kernel_launch(void* const* d_in, const int* in_sizes, int n_in,
                              void* d_out, int out_size) {
    const float* Q    = (const float*)d_in[0];
    const float* K    = (const float*)d_in[1];
    const float* V    = (const float*)d_in[2];
    const float* mask = (const float*)d_in[3];
    const float* curv = (const float*)d_in[4];
    float* out = (float*)d_out;
    (void)in_sizes; (void)n_in; (void)out_size;

    k0_zero<<<(BH*Dv*Dv + 255)/256, 256>>>();
    k1_pass1<<<dim3(BH, SPLIT1), 256>>>(K, V, mask, curv);
    k2_pass2<<<dim3(BH, SPLIT2), 256>>>(Q, curv, out);
}

// round 14
// speedup vs baseline: 2.2029x; 1.4427x over previous
#include <cuda_runtime.h>
#include <cuda_bf16.h>
#include <stdint.h>
#include <math.h>

typedef unsigned int u32; typedef unsigned short u16;

#define Nv 8192
#define Dv 64
#define Hv 16
#define BH 64
#define SPLIT1 8
#define SPLIT2 8

// scratch
__device__ float g_ctxT[BH*Dv*Dv];   // [bh][e][d]  (transposed for pass2 B operand)
__device__ float g_v2sum[BH*Dv];     // [bh][d]
__device__ float g_f[BH*Nv];         // per-token denominator

static __device__ __forceinline__ u32 s2u(const void* p){ return (u32)__cvta_generic_to_shared(p); }
static __device__ __forceinline__ float elu1(float x){ return x > 0.f ? x + 1.f : __expf(x); }
static __device__ __forceinline__ void bsplit(float v, u16& h, u16& l){
    __nv_bfloat16 bh = __float2bfloat16_rn(v);
    float r = v - __bfloat162float(bh);
    __nv_bfloat16 bl = __float2bfloat16_rn(r);
    h = __bfloat16_as_ushort(bh); l = __bfloat16_as_ushort(bl);
}
static __device__ __forceinline__ u32 pk(u16 a, u16 b){ return (u32)a | ((u32)b << 16); }
static __device__ __forceinline__ void sts128(u32 a, u32 x, u32 y, u32 z, u32 w){
    asm volatile("st.shared.v4.b32 [%0], {%1,%2,%3,%4};" :: "r"(a), "r"(x), "r"(y), "r"(z), "r"(w) : "memory");
}
static __device__ __forceinline__ void ldm4t(u32* r, u32 a){
    asm volatile("ldmatrix.sync.aligned.m8n8.x4.trans.shared.b16 {%0,%1,%2,%3}, [%4];"
        : "=r"(r[0]), "=r"(r[1]), "=r"(r[2]), "=r"(r[3]) : "r"(a));
}
static __device__ __forceinline__ void ldm4(u32* r, u32 a){
    asm volatile("ldmatrix.sync.aligned.m8n8.x4.shared.b16 {%0,%1,%2,%3}, [%4];"
        : "=r"(r[0]), "=r"(r[1]), "=r"(r[2]), "=r"(r[3]) : "r"(a));
}
static __device__ __forceinline__ void mmabf(float* c, const u32* a, u32 b0, u32 b1){
    asm volatile("mma.sync.aligned.m16n8k16.row.col.f32.bf16.bf16.f32 "
        "{%0,%1,%2,%3}, {%4,%5,%6,%7}, {%8,%9}, {%0,%1,%2,%3};"
        : "+f"(c[0]), "+f"(c[1]), "+f"(c[2]), "+f"(c[3])
        : "r"(a[0]), "r"(a[1]), "r"(a[2]), "r"(a[3]), "r"(b0), "r"(b1));
}

__global__ void k0_zero(){
    int i = blockIdx.x*blockDim.x + threadIdx.x;
    if (i < BH*Dv*Dv) g_ctxT[i] = 0.f;
    if (i < BH*Dv)    g_v2sum[i] = 0.f;
}

// ---------------- Pass 1: ctxT[e][d] = sum_t x[t][e] * v2[t][d] via mma.sync ----------------
__global__ __launch_bounds__(256) void k1_pass1(
        const float* __restrict__ Kin, const float* __restrict__ Vin,
        const float* __restrict__ mask, const float* __restrict__ curv){
    __shared__ __align__(16) u16 twh[32*72], twl[32*72], txh[32*72], txl[32*72];
    __shared__ float smv[Dv];
    const int bh = blockIdx.x, split = blockIdx.y;
    const float kc = curv[bh & (Hv-1)];
    const int tid = threadIdx.x, w = tid>>5, lane = tid&31;
    if (tid < Dv) smv[tid] = 0.f;
    const float* Kb = Kin + (size_t)bh*Nv*Dv;
    const float* Vb = Vin + (size_t)bh*Nv*Dv;
    const int t8 = tid>>3, sub = tid&7;
    const int dbase = 16*(w&3), ebase = 32*(w>>2);
    const u32 WH = s2u(twh), WL = s2u(twl), XH = s2u(txh), XL = s2u(txl);

    float acc[16];
    #pragma unroll
    for (int i = 0; i < 16; i++) acc[i] = 0.f;
    float v2loc[8];
    #pragma unroll
    for (int j = 0; j < 8; j++) v2loc[j] = 0.f;

    for (int tile = 0; tile < (Nv/SPLIT1)/32; ++tile){
        const int n0 = split*(Nv/SPLIT1) + tile*32;
        __syncthreads();   // tiles free (prev GEMM done)
        // Phase AB: gmem -> scalars -> bf16 hi/lo tiles [t][*]
        {
            size_t ro = ((size_t)(n0 + t8))*Dv + sub*8;
            float4 ka = *(const float4*)(Kb + ro);
            float4 kb4 = *(const float4*)(Kb + ro + 4);
            float4 va = *(const float4*)(Vb + ro);
            float4 vb4 = *(const float4*)(Vb + ro + 4);
            float ss = va.x*va.x + va.y*va.y + va.z*va.z + va.w*va.w
                     + vb4.x*vb4.x + vb4.y*vb4.y + vb4.z*vb4.z + vb4.w*vb4.w;
            ss += __shfl_xor_sync(~0u, ss, 1);
            ss += __shfl_xor_sync(~0u, ss, 2);
            ss += __shfl_xor_sync(~0u, ss, 4);
            float f = fmaxf(1.f + kc*ss, 1e-15f);
            float invf = 1.f/f;
            float gamma = 2.f*invf;
            float gm1 = gamma - 1.f;
            float dn = copysignf(fmaxf(fabsf(gm1), 1e-10f), gm1);
            float m = mask[n0 + t8];
            float dm = dn*m, gd = (gamma/dn)*m;
            float wv[8], xv[8];
            wv[0]=dm*elu1(ka.x*invf);  wv[1]=dm*elu1(ka.y*invf);
            wv[2]=dm*elu1(ka.z*invf);  wv[3]=dm*elu1(ka.w*invf);
            wv[4]=dm*elu1(kb4.x*invf); wv[5]=dm*elu1(kb4.y*invf);
            wv[6]=dm*elu1(kb4.z*invf); wv[7]=dm*elu1(kb4.w*invf);
            xv[0]=gd*va.x;  xv[1]=gd*va.y;  xv[2]=gd*va.z;  xv[3]=gd*va.w;
            xv[4]=gd*vb4.x; xv[5]=gd*vb4.y; xv[6]=gd*vb4.z; xv[7]=gd*vb4.w;
            #pragma unroll
            for (int j = 0; j < 8; j++) v2loc[j] += wv[j];
            u16 h[8], l[8];
            #pragma unroll
            for (int j = 0; j < 8; j++) bsplit(wv[j], h[j], l[j]);
            u32 off = (u32)(t8*72 + sub*8)*2;
            sts128(WH + off, pk(h[0],h[1]), pk(h[2],h[3]), pk(h[4],h[5]), pk(h[6],h[7]));
            sts128(WL + off, pk(l[0],l[1]), pk(l[2],l[3]), pk(l[4],l[5]), pk(l[6],l[7]));
            #pragma unroll
            for (int j = 0; j < 8; j++) bsplit(xv[j], h[j], l[j]);
            sts128(XH + off, pk(h[0],h[1]), pk(h[2],h[3]), pk(h[4],h[5]), pk(h[6],h[7]));
            sts128(XL + off, pk(l[0],l[1]), pk(l[2],l[3]), pk(l[4],l[5]), pk(l[6],l[7]));
            if (sub == 0) g_f[(size_t)bh*Nv + n0 + t8] = f;
        }
        __syncthreads();
        // GEMM: acc[d16 x e32] += A(=v2^T)[d][t] * B(=x)[t][e], 2 k-steps of 16 tokens
        #pragma unroll
        for (int ks = 0; ks < 2; ks++){
            const int kb = ks*16;
            // A-frag via trans-ldmatrix: matrix bits: (lane>>3)&1 -> d half, (lane>>4)&1 -> t half
            u32 aoff = (u32)((kb + (lane&7) + 8*((lane>>4)&1))*72 + dbase + 8*((lane>>3)&1))*2;
            u32 ah[4], al[4];
            ldm4t(ah, WH + aoff);
            ldm4t(al, WL + aoff);
            // B-frags via trans-ldmatrix: (lane>>3)&1 -> k half, (lane>>4)&1 -> n(+8) chunk
            u32 boff0 = (u32)((kb + (lane&7) + 8*((lane>>3)&1))*72 + ebase + 8*((lane>>4)&1))*2;
            u32 boff1 = boff0 + 16*2;
            u32 bh0[4], bh1[4], bl0[4], bl1[4];
            ldm4t(bh0, XH + boff0); ldm4t(bh1, XH + boff1);
            ldm4t(bl0, XL + boff0); ldm4t(bl1, XL + boff1);
            // chains: hh + hl + lh
            mmabf(acc+0,  ah, bh0[0], bh0[1]); mmabf(acc+4,  ah, bh0[2], bh0[3]);
            mmabf(acc+8,  ah, bh1[0], bh1[1]); mmabf(acc+12, ah, bh1[2], bh1[3]);
            mmabf(acc+0,  ah, bl0[0], bl0[1]); mmabf(acc+4,  ah, bl0[2], bl0[3]);
            mmabf(acc+8,  ah, bl1[0], bl1[1]); mmabf(acc+12, ah, bl1[2], bl1[3]);
            mmabf(acc+0,  al, bh0[0], bh0[1]); mmabf(acc+4,  al, bh0[2], bh0[3]);
            mmabf(acc+8,  al, bh1[0], bh1[1]); mmabf(acc+12, al, bh1[2], bh1[3]);
        }
    }
    // epilogue: frag (row=d, col=e) -> g_ctxT[e][d]
    float* ctxT = g_ctxT + bh*Dv*Dv;
    const int dr = dbase + (lane>>2);
    #pragma unroll
    for (int q = 0; q < 4; q++){
        int e0 = ebase + q*8 + 2*(lane&3);
        atomicAdd(&ctxT[(e0  )*Dv + dr    ], acc[q*4+0]);
        atomicAdd(&ctxT[(e0+1)*Dv + dr    ], acc[q*4+1]);
        atomicAdd(&ctxT[(e0  )*Dv + dr + 8], acc[q*4+2]);
        atomicAdd(&ctxT[(e0+1)*Dv + dr + 8], acc[q*4+3]);
    }
    #pragma unroll
    for (int j = 0; j < 8; j++) atomicAdd(&smv[sub*8+j], v2loc[j]);
    __syncthreads();
    if (tid < Dv) atomicAdd(&g_v2sum[bh*Dv + tid], smv[tid]);
}

// ---------------- Pass 2: X = v1 @ ctx via mma.sync + fused radial epilogue ----------------
__global__ __launch_bounds__(256) void k2_pass2(
        const float* __restrict__ Qin, const float* __restrict__ curv,
        float* __restrict__ Out){
    __shared__ __align__(16) u16 ch[64*72], cl[64*72];
    __shared__ __align__(16) char uni[2*64*72*2];   // v1h|v1l during GEMM, obuf after
    __shared__ float v2s[Dv], dinvv[64], rowss[64];
    const int bh = blockIdx.x, split = blockIdx.y;
    const float kc = curv[bh & (Hv-1)];
    const float absk = fabsf(kc);
    const float sk = sqrtf(absk + 1e-15f);
    const float maxnorm = (kc < 0.f) ? (1.f - 0.004f)/sqrtf(absk + 1e-15f) : 1e15f;
    const int tid = threadIdx.x, w = tid>>5, lane = tid&31;
    const u32 CH = s2u(ch), CL = s2u(cl);
    const u32 V1H = s2u(uni), V1L = V1H + 64*72*2;
    float* obuf = (float*)uni;   // [64][68]

    // ctxT -> bf16 hi/lo B tiles [e][d]
    for (int idx = tid; idx < Dv*Dv; idx += 256){
        float c = g_ctxT[bh*Dv*Dv + idx];
        u16 h, l; bsplit(c, h, l);
        ch[(idx>>6)*72 + (idx&63)] = h;
        cl[(idx>>6)*72 + (idx&63)] = l;
    }
    if (tid < Dv) v2s[tid] = g_v2sum[bh*Dv + tid];
    const float* Qb = Qin + (size_t)bh*Nv*Dv;
    float* Ob = Out + (size_t)bh*Nv*Dv;
    const int t4 = tid>>2, sub4 = tid&3, d16 = (tid&3)*16;
    const int tbase = 16*(w&3), ebase = 32*(w>>2);
    __syncthreads();

    for (int tile = 0; tile < (Nv/SPLIT2)/64; ++tile){
        const int n0 = split*(Nv/SPLIT2) + tile*64;
        // Phase A: Q -> v1 hi/lo [t][d] + exact Dn
        {
            float f = g_f[(size_t)bh*Nv + n0 + t4];
            float iv = 1.f/f;
            float ev[16];
            float p = 0.f;
            #pragma unroll
            for (int i = 0; i < 4; i++){
                float4 q = *(const float4*)(Qb + (size_t)(n0 + t4)*Dv + d16 + i*4);
                ev[i*4+0] = elu1(q.x*iv); ev[i*4+1] = elu1(q.y*iv);
                ev[i*4+2] = elu1(q.z*iv); ev[i*4+3] = elu1(q.w*iv);
                p += ev[i*4+0]*v2s[d16+i*4] + ev[i*4+1]*v2s[d16+i*4+1]
                   + ev[i*4+2]*v2s[d16+i*4+2] + ev[i*4+3]*v2s[d16+i*4+3];
            }
            p += __shfl_xor_sync(~0u, p, 1);
            p += __shfl_xor_sync(~0u, p, 2);
            if (sub4 == 0) dinvv[t4] = 1.f/((p == 0.f) ? 1e-5f : p);
            u16 h[16], l[16];
            #pragma unroll
            for (int i = 0; i < 16; i++) bsplit(ev[i], h[i], l[i]);
            u32 off = (u32)(t4*72 + d16)*2;
            sts128(V1H + off,      pk(h[0],h[1]),  pk(h[2],h[3]),  pk(h[4],h[5]),  pk(h[6],h[7]));
            sts128(V1H + off + 16, pk(h[8],h[9]),  pk(h[10],h[11]),pk(h[12],h[13]),pk(h[14],h[15]));
            sts128(V1L + off,      pk(l[0],l[1]),  pk(l[2],l[3]),  pk(l[4],l[5]),  pk(l[6],l[7]));
            sts128(V1L + off + 16, pk(l[8],l[9]),  pk(l[10],l[11]),pk(l[12],l[13]),pk(l[14],l[15]));
        }
        __syncthreads();
        // GEMM: C[t16 x e32] = sum_d v1[t][d] * ctxT^T[d][e], 4 k-steps
        float acc[16];
        #pragma unroll
        for (int i = 0; i < 16; i++) acc[i] = 0.f;
        #pragma unroll
        for (int ks = 0; ks < 4; ks++){
            const int kb = ks*16;
            u32 aoff = (u32)((tbase + (lane&15))*72 + kb + 8*((lane>>4)&1))*2;
            u32 ah[4], al[4];
            ldm4(ah, V1H + aoff);
            ldm4(al, V1L + aoff);
            u32 boff0 = (u32)((ebase + (lane&7) + 8*((lane>>4)&1))*72 + kb + 8*((lane>>3)&1))*2;
            u32 boff1 = boff0 + (u32)(16*72)*2;
            u32 bh0[4], bh1[4], bl0[4], bl1[4];
            ldm4(bh0, CH + boff0); ldm4(bh1, CH + boff1);
            ldm4(bl0, CL + boff0); ldm4(bl1, CL + boff1);
            mmabf(acc+0,  ah, bh0[0], bh0[1]); mmabf(acc+4,  ah, bh0[2], bh0[3]);
            mmabf(acc+8,  ah, bh1[0], bh1[1]); mmabf(acc+12, ah, bh1[2], bh1[3]);
            mmabf(acc+0,  ah, bl0[0], bl0[1]); mmabf(acc+4,  ah, bl0[2], bl0[3]);
            mmabf(acc+8,  ah, bl1[0], bl1[1]); mmabf(acc+12, ah, bl1[2], bl1[3]);
            mmabf(acc+0,  al, bh0[0], bh0[1]); mmabf(acc+4,  al, bh0[2], bh0[3]);
            mmabf(acc+8,  al, bh1[0], bh1[1]); mmabf(acc+12, al, bh1[2], bh1[3]);
        }
        __syncthreads();           // all warps done with v1 region
        if (tid < 64) rowss[tid] = 0.f;
        __syncthreads();
        // epilogue stage 1: y = C*dinv, accumulate row sumsq
        const int r0 = tbase + (lane>>2), r1 = r0 + 8;
        float di0 = dinvv[r0], di1 = dinvv[r1];
        {
            float p0 = 0.f, p1 = 0.f;
            #pragma unroll
            for (int q = 0; q < 4; q++){
                float y0 = acc[q*4+0]*di0, y1 = acc[q*4+1]*di0;
                float y2 = acc[q*4+2]*di1, y3 = acc[q*4+3]*di1;
                p0 += y0*y0 + y1*y1;
                p1 += y2*y2 + y3*y3;
            }
            p0 += __shfl_xor_sync(~0u, p0, 1); p0 += __shfl_xor_sync(~0u, p0, 2);
            p1 += __shfl_xor_sync(~0u, p1, 1); p1 += __shfl_xor_sync(~0u, p1, 2);
            if ((lane&3) == 0){ atomicAdd(&rowss[r0], p0); atomicAdd(&rowss[r1], p1); }
        }
        __syncthreads();
        // stage 2: per-token radial scale; fold dinv into it
        if (tid < 64){
            float ss = rowss[tid];
            float norm = fmaxf(sqrtf(ss), 1e-15f);
            float s = 1.f, n1 = norm;
            if (norm > maxnorm){ s = maxnorm/norm; n1 = maxnorm; }
            float xn = fmaxf(n1, 1e-15f);
            float tv;
            if (kc < 0.f){
                float z = fminf(sk*xn, 1.f - 1e-7f);
                tv = z / ((1.f + sqrtf(fmaxf(1.f - z*z, 0.f))) * sk);
            } else {
                tv = tanf(0.5f*atanf(sk*xn)) / sk;
            }
            s *= tv/xn;
            float n2 = fabsf(tv);
            if (n2 > maxnorm) s *= maxnorm/n2;
            rowss[tid] = s * dinvv[tid];    // final multiplier on raw C
        }
        __syncthreads();                    // also: v1 reads done -> obuf may overwrite
        // stage 3: scatter scaled frags to obuf
        {
            float f0 = rowss[r0], f1 = rowss[r1];
            #pragma unroll
            for (int q = 0; q < 4; q++){
                int e0 = ebase + q*8 + 2*(lane&3);
                obuf[r0*68 + e0    ] = acc[q*4+0]*f0;
                obuf[r0*68 + e0 + 1] = acc[q*4+1]*f0;
                obuf[r1*68 + e0    ] = acc[q*4+2]*f1;
                obuf[r1*68 + e0 + 1] = acc[q*4+3]*f1;
            }
        }
        __syncthreads();
        // coalesced flush
        #pragma unroll
        for (int i = 0; i < 4; i++){
            float4 v = *(float4*)&obuf[t4*68 + d16 + i*4];
            *(float4*)(Ob + (size_t)(n0 + t4)*Dv + d16 + i*4) = v;
        }
        __syncthreads();                    // obuf read done -> next phase A may overwrite
    }
}

extern "C" void kernel_launch(void* const* d_in, const int* in_sizes, int n_in,
                              void* d_out, int out_size) {
    const float* Q    = (const float*)d_in[0];
    const float* K    = (const float*)d_in[1];
    const float* V    = (const float*)d_in[2];
    const float* mask = (const float*)d_in[3];
    const float* curv = (const float*)d_in[4];
    float* out = (float*)d_out;
    (void)in_sizes; (void)n_in; (void)out_size;

    k0_zero<<<(BH*Dv*Dv + 255)/256, 256>>>();
    k1_pass1<<<dim3(BH, SPLIT1), 256>>>(K, V, mask, curv);
    k2_pass2<<<dim3(BH, SPLIT2), 256>>>(Q, curv, out);
}

// round 17
// speedup vs baseline: 2.5871x; 1.1744x over previous
#include <cuda_runtime.h>
#include <cuda_bf16.h>
#include <stdint.h>
#include <math.h>

typedef unsigned int u32; typedef unsigned short u16;

#define Nv 8192
#define Dv 64
#define Hv 16
#define BH 64
#define SPLIT1 16
#define SPLIT2 16

// scratch
__device__ float g_ctxT[BH*Dv*Dv];   // [bh][e][d]  (transposed for pass2 B operand)
__device__ float g_v2sum[BH*Dv];     // [bh][d]
__device__ float g_f[BH*Nv];         // per-token denominator

static __device__ __forceinline__ u32 s2u(const void* p){ return (u32)__cvta_generic_to_shared(p); }
static __device__ __forceinline__ float elu1(float x){ return x > 0.f ? x + 1.f : __expf(x); }
static __device__ __forceinline__ void bsplit(float v, u16& h, u16& l){
    __nv_bfloat16 bh = __float2bfloat16_rn(v);
    float r = v - __bfloat162float(bh);
    __nv_bfloat16 bl = __float2bfloat16_rn(r);
    h = __bfloat16_as_ushort(bh); l = __bfloat16_as_ushort(bl);
}
static __device__ __forceinline__ u32 pk(u16 a, u16 b){ return (u32)a | ((u32)b << 16); }
static __device__ __forceinline__ void sts128(u32 a, u32 x, u32 y, u32 z, u32 w){
    asm volatile("st.shared.v4.b32 [%0], {%1,%2,%3,%4};" :: "r"(a), "r"(x), "r"(y), "r"(z), "r"(w) : "memory");
}
static __device__ __forceinline__ void ldm4t(u32* r, u32 a){
    asm volatile("ldmatrix.sync.aligned.m8n8.x4.trans.shared.b16 {%0,%1,%2,%3}, [%4];"
        : "=r"(r[0]), "=r"(r[1]), "=r"(r[2]), "=r"(r[3]) : "r"(a));
}
static __device__ __forceinline__ void ldm4(u32* r, u32 a){
    asm volatile("ldmatrix.sync.aligned.m8n8.x4.shared.b16 {%0,%1,%2,%3}, [%4];"
        : "=r"(r[0]), "=r"(r[1]), "=r"(r[2]), "=r"(r[3]) : "r"(a));
}
static __device__ __forceinline__ void mmabf(float* c, const u32* a, u32 b0, u32 b1){
    asm volatile("mma.sync.aligned.m16n8k16.row.col.f32.bf16.bf16.f32 "
        "{%0,%1,%2,%3}, {%4,%5,%6,%7}, {%8,%9}, {%0,%1,%2,%3};"
        : "+f"(c[0]), "+f"(c[1]), "+f"(c[2]), "+f"(c[3])
        : "r"(a[0]), "r"(a[1]), "r"(a[2]), "r"(a[3]), "r"(b0), "r"(b1));
}

__global__ void k0_zero(){
    int i = blockIdx.x*blockDim.x + threadIdx.x;
    if (i < BH*Dv*Dv) g_ctxT[i] = 0.f;
    if (i < BH*Dv)    g_v2sum[i] = 0.f;
}

// ---------------- Pass 1: ctxT[e][d] = sum_t x[t][e] * v2[t][d] via mma.sync ----------------
__global__ __launch_bounds__(256) void k1_pass1(
        const float* __restrict__ Kin, const float* __restrict__ Vin,
        const float* __restrict__ mask, const float* __restrict__ curv){
    __shared__ __align__(16) u16 twh[32*72], twl[32*72], txh[32*72], txl[32*72];
    __shared__ float smv[Dv];
    const int bh = blockIdx.x, split = blockIdx.y;
    const float kc = curv[bh & (Hv-1)];
    const int tid = threadIdx.x, w = tid>>5, lane = tid&31;
    if (tid < Dv) smv[tid] = 0.f;
    const float* Kb = Kin + (size_t)bh*Nv*Dv;
    const float* Vb = Vin + (size_t)bh*Nv*Dv;
    const int t8 = tid>>3, sub = tid&7;
    const int dbase = 16*(w&3), ebase = 32*(w>>2);
    const u32 WH = s2u(twh), WL = s2u(twl), XH = s2u(txh), XL = s2u(txl);
    const int nbase = split*(Nv/SPLIT1);
    const int NT = (Nv/SPLIT1)/32;   // 16

    float acc[16];
    #pragma unroll
    for (int i = 0; i < 16; i++) acc[i] = 0.f;
    float v2loc[8];
    #pragma unroll
    for (int j = 0; j < 8; j++) v2loc[j] = 0.f;

    // preload tile 0
    float4 ka, kb4, va, vb4;
    {
        size_t ro = ((size_t)(nbase + t8))*Dv + sub*8;
        ka  = *(const float4*)(Kb + ro);  kb4 = *(const float4*)(Kb + ro + 4);
        va  = *(const float4*)(Vb + ro);  vb4 = *(const float4*)(Vb + ro + 4);
    }

    for (int tile = 0; tile < NT; ++tile){
        const int n0 = nbase + tile*32;
        // Phase A: scalars -> bf16 hi/lo tiles [t][*]  (consumes prefetched regs)
        {
            float ss = va.x*va.x + va.y*va.y + va.z*va.z + va.w*va.w
                     + vb4.x*vb4.x + vb4.y*vb4.y + vb4.z*vb4.z + vb4.w*vb4.w;
            ss += __shfl_xor_sync(~0u, ss, 1);
            ss += __shfl_xor_sync(~0u, ss, 2);
            ss += __shfl_xor_sync(~0u, ss, 4);
            float f = fmaxf(1.f + kc*ss, 1e-15f);
            float invf = 1.f/f;
            float gamma = 2.f*invf;
            float gm1 = gamma - 1.f;
            float dn = copysignf(fmaxf(fabsf(gm1), 1e-10f), gm1);
            float m = mask[n0 + t8];
            float dm = dn*m, gd = (gamma/dn)*m;
            float wv[8], xv[8];
            wv[0]=dm*elu1(ka.x*invf);  wv[1]=dm*elu1(ka.y*invf);
            wv[2]=dm*elu1(ka.z*invf);  wv[3]=dm*elu1(ka.w*invf);
            wv[4]=dm*elu1(kb4.x*invf); wv[5]=dm*elu1(kb4.y*invf);
            wv[6]=dm*elu1(kb4.z*invf); wv[7]=dm*elu1(kb4.w*invf);
            xv[0]=gd*va.x;  xv[1]=gd*va.y;  xv[2]=gd*va.z;  xv[3]=gd*va.w;
            xv[4]=gd*vb4.x; xv[5]=gd*vb4.y; xv[6]=gd*vb4.z; xv[7]=gd*vb4.w;
            #pragma unroll
            for (int j = 0; j < 8; j++) v2loc[j] += wv[j];
            u16 h[8], l[8];
            #pragma unroll
            for (int j = 0; j < 8; j++) bsplit(wv[j], h[j], l[j]);
            u32 off = (u32)(t8*72 + sub*8)*2;
            sts128(WH + off, pk(h[0],h[1]), pk(h[2],h[3]), pk(h[4],h[5]), pk(h[6],h[7]));
            sts128(WL + off, pk(l[0],l[1]), pk(l[2],l[3]), pk(l[4],l[5]), pk(l[6],l[7]));
            #pragma unroll
            for (int j = 0; j < 8; j++) bsplit(xv[j], h[j], l[j]);
            sts128(XH + off, pk(h[0],h[1]), pk(h[2],h[3]), pk(h[4],h[5]), pk(h[6],h[7]));
            sts128(XL + off, pk(l[0],l[1]), pk(l[2],l[3]), pk(l[4],l[5]), pk(l[6],l[7]));
            if (sub == 0) g_f[(size_t)bh*Nv + n0 + t8] = f;
        }
        __syncthreads();
        // Prefetch next tile (hidden behind GEMM)
        if (tile + 1 < NT){
            size_t ro = ((size_t)(n0 + 32 + t8))*Dv + sub*8;
            ka  = *(const float4*)(Kb + ro);  kb4 = *(const float4*)(Kb + ro + 4);
            va  = *(const float4*)(Vb + ro);  vb4 = *(const float4*)(Vb + ro + 4);
        }
        // GEMM: acc[d16 x e32] += A(=v2^T)[d][t] * B(=x)[t][e], 2 k-steps of 16 tokens
        #pragma unroll
        for (int ks = 0; ks < 2; ks++){
            const int kb = ks*16;
            u32 aoff = (u32)((kb + (lane&7) + 8*((lane>>4)&1))*72 + dbase + 8*((lane>>3)&1))*2;
            u32 ah[4], al[4];
            ldm4t(ah, WH + aoff);
            ldm4t(al, WL + aoff);
            u32 boff0 = (u32)((kb + (lane&7) + 8*((lane>>3)&1))*72 + ebase + 8*((lane>>4)&1))*2;
            u32 boff1 = boff0 + 16*2;
            u32 bh0[4], bh1[4], bl0[4], bl1[4];
            ldm4t(bh0, XH + boff0); ldm4t(bh1, XH + boff1);
            ldm4t(bl0, XL + boff0); ldm4t(bl1, XL + boff1);
            mmabf(acc+0,  ah, bh0[0], bh0[1]); mmabf(acc+4,  ah, bh0[2], bh0[3]);
            mmabf(acc+8,  ah, bh1[0], bh1[1]); mmabf(acc+12, ah, bh1[2], bh1[3]);
            mmabf(acc+0,  ah, bl0[0], bl0[1]); mmabf(acc+4,  ah, bl0[2], bl0[3]);
            mmabf(acc+8,  ah, bl1[0], bl1[1]); mmabf(acc+12, ah, bl1[2], bl1[3]);
            mmabf(acc+0,  al, bh0[0], bh0[1]); mmabf(acc+4,  al, bh0[2], bh0[3]);
            mmabf(acc+8,  al, bh1[0], bh1[1]); mmabf(acc+12, al, bh1[2], bh1[3]);
        }
        __syncthreads();
    }
    // epilogue: frag (row=d, col=e) -> g_ctxT[e][d]
    float* ctxT = g_ctxT + bh*Dv*Dv;
    const int dr = dbase + (lane>>2);
    #pragma unroll
    for (int q = 0; q < 4; q++){
        int e0 = ebase + q*8 + 2*(lane&3);
        atomicAdd(&ctxT[(e0  )*Dv + dr    ], acc[q*4+0]);
        atomicAdd(&ctxT[(e0+1)*Dv + dr    ], acc[q*4+1]);
        atomicAdd(&ctxT[(e0  )*Dv + dr + 8], acc[q*4+2]);
        atomicAdd(&ctxT[(e0+1)*Dv + dr + 8], acc[q*4+3]);
    }
    #pragma unroll
    for (int j = 0; j < 8; j++) atomicAdd(&smv[sub*8+j], v2loc[j]);
    __syncthreads();
    if (tid < Dv) atomicAdd(&g_v2sum[bh*Dv + tid], smv[tid]);
}

// ---------------- Pass 2: X = v1 @ ctx via mma.sync + fused radial epilogue ----------------
__global__ __launch_bounds__(256) void k2_pass2(
        const float* __restrict__ Qin, const float* __restrict__ curv,
        float* __restrict__ Out){
    __shared__ __align__(16) u16 ch[64*72], cl[64*72];
    __shared__ __align__(16) u16 v1h[64*72], v1l[64*72];
    __shared__ float v2s[Dv], dinvv[2][64], rowss[2][64];
    const int bh = blockIdx.x, split = blockIdx.y;
    const float kc = curv[bh & (Hv-1)];
    const float absk = fabsf(kc);
    const float sk = sqrtf(absk + 1e-15f);
    const float maxnorm = (kc < 0.f) ? (1.f - 0.004f)/sqrtf(absk + 1e-15f) : 1e15f;
    const int tid = threadIdx.x, w = tid>>5, lane = tid&31;
    const u32 CH = s2u(ch), CL = s2u(cl);
    const u32 V1H = s2u(v1h), V1L = s2u(v1l);

    // ctxT -> bf16 hi/lo B tiles [e][d]
    for (int idx = tid; idx < Dv*Dv; idx += 256){
        float c = g_ctxT[bh*Dv*Dv + idx];
        u16 h, l; bsplit(c, h, l);
        ch[(idx>>6)*72 + (idx&63)] = h;
        cl[(idx>>6)*72 + (idx&63)] = l;
    }
    if (tid < Dv) v2s[tid] = g_v2sum[bh*Dv + tid];
    const float* Qb = Qin + (size_t)bh*Nv*Dv;
    float* Ob = Out + (size_t)bh*Nv*Dv;
    const int t4 = tid>>2, sub4 = tid&3, d16 = (tid&3)*16;
    const int tbase = 16*(w&3), ebase = 32*(w>>2);
    const int nbase = split*(Nv/SPLIT2);
    const int NT = (Nv/SPLIT2)/64;   // 8
    __syncthreads();

    // preload tile 0
    float4 qreg[4]; float fcur;
    {
        fcur = g_f[(size_t)bh*Nv + nbase + t4];
        #pragma unroll
        for (int i = 0; i < 4; i++)
            qreg[i] = *(const float4*)(Qb + (size_t)(nbase + t4)*Dv + d16 + i*4);
    }

    for (int tile = 0; tile < NT; ++tile){
        const int n0 = nbase + tile*64;
        const int pb = tile & 1;
        // Phase A: v1 hi/lo [t][d] + exact Dn (consumes prefetched regs)
        {
            float iv = 1.f/fcur;
            float ev[16];
            float p = 0.f;
            #pragma unroll
            for (int i = 0; i < 4; i++){
                float4 q = qreg[i];
                ev[i*4+0] = elu1(q.x*iv); ev[i*4+1] = elu1(q.y*iv);
                ev[i*4+2] = elu1(q.z*iv); ev[i*4+3] = elu1(q.w*iv);
                p += ev[i*4+0]*v2s[d16+i*4] + ev[i*4+1]*v2s[d16+i*4+1]
                   + ev[i*4+2]*v2s[d16+i*4+2] + ev[i*4+3]*v2s[d16+i*4+3];
            }
            p += __shfl_xor_sync(~0u, p, 1);
            p += __shfl_xor_sync(~0u, p, 2);
            if (sub4 == 0) dinvv[pb][t4] = 1.f/((p == 0.f) ? 1e-5f : p);
            u16 h[16], l[16];
            #pragma unroll
            for (int i = 0; i < 16; i++) bsplit(ev[i], h[i], l[i]);
            u32 off = (u32)(t4*72 + d16)*2;
            sts128(V1H + off,      pk(h[0],h[1]),  pk(h[2],h[3]),  pk(h[4],h[5]),  pk(h[6],h[7]));
            sts128(V1H + off + 16, pk(h[8],h[9]),  pk(h[10],h[11]),pk(h[12],h[13]),pk(h[14],h[15]));
            sts128(V1L + off,      pk(l[0],l[1]),  pk(l[2],l[3]),  pk(l[4],l[5]),  pk(l[6],l[7]));
            sts128(V1L + off + 16, pk(l[8],l[9]),  pk(l[10],l[11]),pk(l[12],l[13]),pk(l[14],l[15]));
            if (tid < 64) rowss[pb][tid] = 0.f;
        }
        __syncthreads();   // A: v1/dinv/rowss-zero visible
        // Prefetch next tile (hidden behind GEMM)
        if (tile + 1 < NT){
            fcur = g_f[(size_t)bh*Nv + n0 + 64 + t4];
            #pragma unroll
            for (int i = 0; i < 4; i++)
                qreg[i] = *(const float4*)(Qb + (size_t)(n0 + 64 + t4)*Dv + d16 + i*4);
        }
        // GEMM: C[t16 x e32] = sum_d v1[t][d] * ctxT^T[d][e], 4 k-steps
        float acc[16];
        #pragma unroll
        for (int i = 0; i < 16; i++) acc[i] = 0.f;
        #pragma unroll
        for (int ks = 0; ks < 4; ks++){
            const int kb = ks*16;
            u32 aoff = (u32)((tbase + (lane&15))*72 + kb + 8*((lane>>4)&1))*2;
            u32 ah[4], al[4];
            ldm4(ah, V1H + aoff);
            ldm4(al, V1L + aoff);
            u32 boff0 = (u32)((ebase + (lane&7) + 8*((lane>>4)&1))*72 + kb + 8*((lane>>3)&1))*2;
            u32 boff1 = boff0 + (u32)(16*72)*2;
            u32 bh0[4], bh1[4], bl0[4], bl1[4];
            ldm4(bh0, CH + boff0); ldm4(bh1, CH + boff1);
            ldm4(bl0, CL + boff0); ldm4(bl1, CL + boff1);
            mmabf(acc+0,  ah, bh0[0], bh0[1]); mmabf(acc+4,  ah, bh0[2], bh0[3]);
            mmabf(acc+8,  ah, bh1[0], bh1[1]); mmabf(acc+12, ah, bh1[2], bh1[3]);
            mmabf(acc+0,  ah, bl0[0], bl0[1]); mmabf(acc+4,  ah, bl0[2], bl0[3]);
            mmabf(acc+8,  ah, bl1[0], bl1[1]); mmabf(acc+12, ah, bl1[2], bl1[3]);
            mmabf(acc+0,  al, bh0[0], bh0[1]); mmabf(acc+4,  al, bh0[2], bh0[3]);
            mmabf(acc+8,  al, bh1[0], bh1[1]); mmabf(acc+12, al, bh1[2], bh1[3]);
        }
        // row sumsq partials (y = C*dinv)
        const int r0 = tbase + (lane>>2), r1 = r0 + 8;
        {
            float di0 = dinvv[pb][r0], di1 = dinvv[pb][r1];
            float p0 = 0.f, p1 = 0.f;
            #pragma unroll
            for (int q = 0; q < 4; q++){
                float y0 = acc[q*4+0]*di0, y1 = acc[q*4+1]*di0;
                float y2 = acc[q*4+2]*di1, y3 = acc[q*4+3]*di1;
                p0 += y0*y0 + y1*y1;
                p1 += y2*y2 + y3*y3;
            }
            p0 += __shfl_xor_sync(~0u, p0, 1); p0 += __shfl_xor_sync(~0u, p0, 2);
            p1 += __shfl_xor_sync(~0u, p1, 1); p1 += __shfl_xor_sync(~0u, p1, 2);
            if ((lane&3) == 0){ atomicAdd(&rowss[pb][r0], p0); atomicAdd(&rowss[pb][r1], p1); }
        }
        __syncthreads();   // B: rowss complete; v1 region free for next phase A
        // per-thread radial scale (redundant compute kills a broadcast sync) + direct STG
        {
            float fin[2];
            #pragma unroll
            for (int h2 = 0; h2 < 2; h2++){
                int r = h2 ? r1 : r0;
                float ss = rowss[pb][r];
                float norm = fmaxf(sqrtf(ss), 1e-15f);
                float s = 1.f, n1 = norm;
                if (norm > maxnorm){ s = maxnorm/norm; n1 = maxnorm; }
                float xn = fmaxf(n1, 1e-15f);
                float tv;
                if (kc < 0.f){
                    float z = fminf(sk*xn, 1.f - 1e-7f);
                    tv = z / ((1.f + sqrtf(fmaxf(1.f - z*z, 0.f))) * sk);
                } else {
                    tv = tanf(0.5f*atanf(sk*xn)) / sk;
                }
                s *= tv/xn;
                float n2 = fabsf(tv);
                if (n2 > maxnorm) s *= maxnorm/n2;
                fin[h2] = s * dinvv[pb][r];
            }
            #pragma unroll
            for (int q = 0; q < 4; q++){
                int e0 = ebase + q*8 + 2*(lane&3);
                float2 o0 = make_float2(acc[q*4+0]*fin[0], acc[q*4+1]*fin[0]);
                float2 o1 = make_float2(acc[q*4+2]*fin[1], acc[q*4+3]*fin[1]);
                *(float2*)(Ob + (size_t)(n0 + r0)*Dv + e0) = o0;
                *(float2*)(Ob + (size_t)(n0 + r1)*Dv + e0) = o1;
            }
        }
    }
}

extern "C" void kernel_launch(void* const* d_in, const int* in_sizes, int n_in,
                              void* d_out, int out_size) {
    const float* Q    = (const float*)d_in[0];
    const float* K    = (const float*)d_in[1];
    const float* V    = (const float*)d_in[2];
    const float* mask = (const float*)d_in[3];
    const float* curv = (const float*)d_in[4];
    float* out = (float*)d_out;
    (void)in_sizes; (void)n_in; (void)out_size;

    k0_zero<<<(BH*Dv*Dv + 255)/256, 256>>>();
    k1_pass1<<<dim3(BH, SPLIT1), 256>>>(K, V, mask, curv);
    k2_pass2<<<dim3(BH, SPLIT2), 256>>>(Q, curv, out);
}